// round 6
// baseline (speedup 1.0000x reference)
#include <cuda_runtime.h>
#include <cuda_bf16.h>

// Problem constants
#define BB 32
#define CC 64
#define TT 4096
#define NVEC ((BB * CC * TT) / 4)   // 2,097,152 float4 vectors
#define TVEC (TT / 4)               // 1024 (power of two)

#define GRID 1024
#define BLOCK 256
#define NWARPS (BLOCK / 32)
#define ITERS (NVEC / (GRID * BLOCK))   // exactly 8
#define CHUNK 4                          // float4-pairs per load batch

__device__ float g_partials[GRID];
__device__ unsigned int g_done_count = 0;   // self-resetting per launch

__device__ __forceinline__ float block_reduce(float x)
{
    __shared__ float swarp[NWARPS];
    #pragma unroll
    for (int off = 16; off > 0; off >>= 1)
        x += __shfl_down_sync(0xFFFFFFFFu, x, off);
    int lane = threadIdx.x & 31;
    int wid  = threadIdx.x >> 5;
    if (lane == 0) swarp[wid] = x;
    __syncthreads();
    if (wid == 0) {
        x = (lane < NWARPS) ? swarp[lane] : 0.0f;
        #pragma unroll
        for (int off = NWARPS / 2; off > 0; off >>= 1)
            x += __shfl_down_sync(0xFFFFFFFFu, x, off);
    }
    return x;  // valid in thread 0
}

// minBlocksPerMultiprocessor = 1: release the register cap so ptxas keeps the
// front-batched loads live (MLP ~8/thread) instead of clamping to 32 regs.
__global__ __launch_bounds__(BLOCK, 1) void wass_fused_kernel(
    const float4* __restrict__ yp, const float4* __restrict__ yt,
    float* __restrict__ out)
{
    const int v0 = blockIdx.x * BLOCK + threadIdx.x;
    const int S  = GRID * BLOCK;

    float acc = 0.0f;

    #pragma unroll
    for (int c = 0; c < ITERS / CHUNK; c++) {
        float4 p0, p1, p2, p3, t0, t1, t2, t3;
        const int vbase = v0 + c * CHUNK * S;

        // Front-batched loads: 8 LDG.128 in flight before any compute.
        p0 = yp[vbase + 0 * S];
        t0 = yt[vbase + 0 * S];
        p1 = yp[vbase + 1 * S];
        t1 = yt[vbase + 1 * S];
        p2 = yp[vbase + 2 * S];
        t2 = yt[vbase + 2 * S];
        p3 = yp[vbase + 3 * S];
        t3 = yt[vbase + 3 * S];

        float w0 = (float)(TT - 4 * ((vbase + 0 * S) & (TVEC - 1)));
        float w1 = (float)(TT - 4 * ((vbase + 1 * S) & (TVEC - 1)));
        float w2 = (float)(TT - 4 * ((vbase + 2 * S) & (TVEC - 1)));
        float w3 = (float)(TT - 4 * ((vbase + 3 * S) & (TVEC - 1)));

        acc += fabsf(p0.x - t0.x) * w0 + fabsf(p0.y - t0.y) * (w0 - 1.0f)
             + fabsf(p0.z - t0.z) * (w0 - 2.0f) + fabsf(p0.w - t0.w) * (w0 - 3.0f);
        acc += fabsf(p1.x - t1.x) * w1 + fabsf(p1.y - t1.y) * (w1 - 1.0f)
             + fabsf(p1.z - t1.z) * (w1 - 2.0f) + fabsf(p1.w - t1.w) * (w1 - 3.0f);
        acc += fabsf(p2.x - t2.x) * w2 + fabsf(p2.y - t2.y) * (w2 - 1.0f)
             + fabsf(p2.z - t2.z) * (w2 - 2.0f) + fabsf(p2.w - t2.w) * (w2 - 3.0f);
        acc += fabsf(p3.x - t3.x) * w3 + fabsf(p3.y - t3.y) * (w3 - 1.0f)
             + fabsf(p3.z - t3.z) * (w3 - 2.0f) + fabsf(p3.w - t3.w) * (w3 - 3.0f);
    }

    float bsum = block_reduce(acc);

    __shared__ bool s_is_last;
    if (threadIdx.x == 0) {
        g_partials[blockIdx.x] = bsum;
        __threadfence();                       // partial visible before counting
        unsigned int n = atomicAdd(&g_done_count, 1u);
        s_is_last = (n == GRID - 1);
        if (s_is_last) g_done_count = 0;       // reset for next graph replay
    }
    __syncthreads();

    if (s_is_last) {
        // Deterministic final reduce: fixed order over g_partials.
        float a = 0.0f;
        #pragma unroll 4
        for (int i = threadIdx.x; i < GRID; i += BLOCK)
            a += g_partials[i];
        float total = block_reduce(a);
        if (threadIdx.x == 0) {
            double scaling = 2.0 / ((double)TT * (double)CC * (double)(TT + 1));
            out[0] = (float)((double)total * scaling / (double)BB);
        }
    }
}

extern "C" void kernel_launch(void* const* d_in, const int* in_sizes, int n_in,
                              void* d_out, int out_size)
{
    const float4* yp = reinterpret_cast<const float4*>(d_in[0]);
    const float4* yt = reinterpret_cast<const float4*>(d_in[1]);
    float* out = reinterpret_cast<float*>(d_out);
    wass_fused_kernel<<<GRID, BLOCK>>>(yp, yt, out);
}

// round 7
// speedup vs baseline: 1.2191x; 1.2191x over previous
#include <cuda_runtime.h>
#include <cuda_bf16.h>

// Problem constants
#define BB 32
#define CC 64
#define TT 4096
#define NVEC ((BB * CC * TT) / 4)   // 2,097,152 float4 vectors
#define TVEC (TT / 4)               // 1024 (power of two)

#define GRID 1024
#define BLOCK 256
#define NWARPS (BLOCK / 32)
#define ITERS (NVEC / (GRID * BLOCK))   // exactly 8
#define CHUNK 2                          // float4-pairs per load batch (4 LDG.128)

__device__ float g_partials[GRID];
__device__ unsigned int g_done_count = 0;   // self-resetting per launch

__device__ __forceinline__ float block_reduce(float x)
{
    __shared__ float swarp[NWARPS];
    #pragma unroll
    for (int off = 16; off > 0; off >>= 1)
        x += __shfl_down_sync(0xFFFFFFFFu, x, off);
    int lane = threadIdx.x & 31;
    int wid  = threadIdx.x >> 5;
    if (lane == 0) swarp[wid] = x;
    __syncthreads();
    if (wid == 0) {
        x = (lane < NWARPS) ? swarp[lane] : 0.0f;
        #pragma unroll
        for (int off = NWARPS / 2; off > 0; off >>= 1)
            x += __shfl_down_sync(0xFFFFFFFFu, x, off);
    }
    return x;  // valid in thread 0
}

// Pin regs<=32 (8 CTAs/SM, occ ~83%) while batching 4 LDG.128 per chunk:
// occupancy AND MLP=4 together — R5 had occ but MLP2, R6 had MLP8 but no occ.
__global__ __launch_bounds__(BLOCK, 8) void wass_fused_kernel(
    const float4* __restrict__ yp, const float4* __restrict__ yt,
    float* __restrict__ out)
{
    const int v0 = blockIdx.x * BLOCK + threadIdx.x;
    const int S  = GRID * BLOCK;

    float acc = 0.0f;

    #pragma unroll
    for (int c = 0; c < ITERS / CHUNK; c++) {
        const int va = v0 + (2 * c + 0) * S;
        const int vb = v0 + (2 * c + 1) * S;

        // 4 loads front-batched before any compute.
        float4 p0 = yp[va];
        float4 t0 = yt[va];
        float4 p1 = yp[vb];
        float4 t1 = yt[vb];

        float w0 = (float)(TT - 4 * (va & (TVEC - 1)));
        float w1 = (float)(TT - 4 * (vb & (TVEC - 1)));

        acc += fabsf(p0.x - t0.x) * w0 + fabsf(p0.y - t0.y) * (w0 - 1.0f)
             + fabsf(p0.z - t0.z) * (w0 - 2.0f) + fabsf(p0.w - t0.w) * (w0 - 3.0f);
        acc += fabsf(p1.x - t1.x) * w1 + fabsf(p1.y - t1.y) * (w1 - 1.0f)
             + fabsf(p1.z - t1.z) * (w1 - 2.0f) + fabsf(p1.w - t1.w) * (w1 - 3.0f);
    }

    float bsum = block_reduce(acc);

    __shared__ bool s_is_last;
    if (threadIdx.x == 0) {
        g_partials[blockIdx.x] = bsum;
        __threadfence();                       // partial visible before counting
        unsigned int n = atomicAdd(&g_done_count, 1u);
        s_is_last = (n == GRID - 1);
        if (s_is_last) g_done_count = 0;       // reset for next graph replay
    }
    __syncthreads();

    if (s_is_last) {
        // Deterministic final reduce: fixed order over g_partials.
        float a = 0.0f;
        #pragma unroll 4
        for (int i = threadIdx.x; i < GRID; i += BLOCK)
            a += g_partials[i];
        float total = block_reduce(a);
        if (threadIdx.x == 0) {
            double scaling = 2.0 / ((double)TT * (double)CC * (double)(TT + 1));
            out[0] = (float)((double)total * scaling / (double)BB);
        }
    }
}

extern "C" void kernel_launch(void* const* d_in, const int* in_sizes, int n_in,
                              void* d_out, int out_size)
{
    const float4* yp = reinterpret_cast<const float4*>(d_in[0]);
    const float4* yt = reinterpret_cast<const float4*>(d_in[1]);
    float* out = reinterpret_cast<float*>(d_out);
    wass_fused_kernel<<<GRID, BLOCK>>>(yp, yt, out);
}